// round 2
// baseline (speedup 1.0000x reference)
#include <cuda_runtime.h>
#include <cuda_bf16.h>

// MultiPrototypeLoss: B=16384 rows, C=1000 classes, P=4 prototypes/class.
// d[b,c] = -logsumexp(-x[b, c*4 .. c*4+3])
// in = d[b, label[b]]; out_mean = (sum_c d - in) / (C-1)
// loss = mean_b (in^2 / out_mean^2)
//
// HBM-bound: 262MB single-pass streaming read.
// Labels: JAX without x64 silently makes these int32 despite dtype=jnp.int64
// in the reference. We runtime-detect the layout (odd int32 words all zero
// <=> genuine int64 little-endian) to be robust either way.

#define NUM_P 4
#define NUM_C 1000
#define THREADS 128
#define ITERS ((NUM_C + THREADS - 1) / THREADS)   // 8

__device__ double g_acc;
__device__ int g_labels_are_i64;   // 1 if labels buffer is int64, 0 if int32

// Zero accumulator + detect label dtype.
// Reads exactly n_words int32 (= label element count) — the minimum buffer
// size whether labels are int32 (n words) or int64 (2n words).
__global__ void mpl_init_kernel(const int* __restrict__ labels_raw, int n_words) {
    __shared__ int s_any_odd_nonzero;
    if (threadIdx.x == 0) { s_any_odd_nonzero = 0; g_acc = 0.0; }
    __syncthreads();
    int any = 0;
    for (int i = threadIdx.x; i < n_words / 2; i += blockDim.x) {
        if (labels_raw[2 * i + 1] != 0) any = 1;
    }
    if (__syncthreads_or(any)) {
        if (threadIdx.x == 0) s_any_odd_nonzero = 1;
    }
    __syncthreads();
    if (threadIdx.x == 0) {
        // int64 labels (0..999) little-endian => every odd word is 0.
        // int32 labels => odd words are random labels, ~surely some nonzero.
        g_labels_are_i64 = s_any_odd_nonzero ? 0 : 1;
    }
}

__global__ __launch_bounds__(THREADS) void mpl_main_kernel(
    const float4* __restrict__ dist,      // [B, 1000] float4 groups
    const void* __restrict__ labels_raw)  // [B] int32 or int64
{
    const int row = blockIdx.x;
    const float4* rowp = dist + (size_t)row * NUM_C;
    const int tid = threadIdx.x;

    int lbl;
    if (g_labels_are_i64) {
        lbl = (int)((const long long*)labels_raw)[row];
    } else {
        lbl = ((const int*)labels_raw)[row];
    }

    float sum_d = 0.0f;
    float in_cls = 0.0f;

#pragma unroll
    for (int i = 0; i < ITERS; i++) {
        int cls = i * THREADS + tid;
        if (cls < NUM_C) {
            float4 v = rowp[cls];
            float m = fminf(fminf(v.x, v.y), fminf(v.z, v.w));
            // -logsumexp(-x) = m - log(sum exp(m - x)), m = min(x)
            float s = __expf(m - v.x) + __expf(m - v.y) +
                      __expf(m - v.z) + __expf(m - v.w);
            float d = m - __logf(s);
            sum_d += d;
            if (cls == lbl) in_cls = d;
        }
    }

    // warp reduce (in_cls nonzero on exactly one thread, so sum works)
#pragma unroll
    for (int off = 16; off > 0; off >>= 1) {
        sum_d  += __shfl_xor_sync(0xFFFFFFFFu, sum_d,  off);
        in_cls += __shfl_xor_sync(0xFFFFFFFFu, in_cls, off);
    }

    __shared__ float s_sum[THREADS / 32];
    __shared__ float s_in[THREADS / 32];
    int wid = tid >> 5;
    int lid = tid & 31;
    if (lid == 0) { s_sum[wid] = sum_d; s_in[wid] = in_cls; }
    __syncthreads();

    if (tid == 0) {
        float tot = 0.0f, inc = 0.0f;
#pragma unroll
        for (int w = 0; w < THREADS / 32; w++) { tot += s_sum[w]; inc += s_in[w]; }
        float out_mean = (tot - inc) * (1.0f / (NUM_C - 1));
        float ratio = (inc * inc) / (out_mean * out_mean);
        atomicAdd(&g_acc, (double)ratio);
    }
}

__global__ void mpl_finalize_kernel(float* __restrict__ out, int B) {
    *out = (float)(g_acc / (double)B);
}

extern "C" void kernel_launch(void* const* d_in, const int* in_sizes, int n_in,
                              void* d_out, int out_size) {
    const float4* dist = (const float4*)d_in[0];
    const void* labels = d_in[1];
    float* out = (float*)d_out;
    const int B = in_sizes[1];  // label count == batch size

    mpl_init_kernel<<<1, 256>>>((const int*)labels, B);
    mpl_main_kernel<<<B, THREADS>>>(dist, labels);
    mpl_finalize_kernel<<<1, 1>>>(out, B);
}

// round 3
// speedup vs baseline: 1.2078x; 1.2078x over previous
#include <cuda_runtime.h>
#include <cuda_bf16.h>

// MultiPrototypeLoss — single persistent kernel.
// B=16384 rows, C=1000 classes, P=4 prototypes/class; 262MB once-read stream.
// d[b,c] = -logsumexp(-x[b,4c..4c+3]); loss = mean_b (d[b,l]^2 / out_mean^2).
//
// Label dtype (int32 vs int64, JAX x64 ambiguity) is detected inline per
// block from the first 256 odd int32 words: genuine little-endian int64
// labels in [0,1000) have ALL odd words zero; int32 labels make them random
// labels (P(all 256 zero) ~ 1e-768).

#define NUM_C   1000
#define THREADS 256
#define GRID    (148 * 8)   // persistent: 8 blocks/SM @ 256 thr = 2048 thr/SM

__device__ double   g_acc   = 0.0;
__device__ unsigned g_count = 0u;

__device__ __forceinline__ float softmin4(float4 v) {
    float m = fminf(fminf(v.x, v.y), fminf(v.z, v.w));
    float s = __expf(m - v.x) + __expf(m - v.y) +
              __expf(m - v.z) + __expf(m - v.w);
    return m - __logf(s);   // = -logsumexp(-v)
}

__global__ __launch_bounds__(THREADS) void mpl_kernel(
    const float4* __restrict__ dist,       // [B, NUM_C] float4 groups
    const int*    __restrict__ labels_raw, // [B] int32 OR [B] int64 (as words)
    float*        __restrict__ out,
    int B)
{
    const int tid = threadIdx.x;

    // --- inline label-dtype detection (per block, ~1KB broadcast read) ---
    int odd_idx = 2 * tid + 1;                       // words 1,3,...,511
    int nz = (odd_idx < B) ? (labels_raw[odd_idx] != 0) : 0;
    const int labels_are_i32 = __syncthreads_or(nz);

    __shared__ float s_sum[THREADS / 32];
    __shared__ float s_in [THREADS / 32];
    const int wid = tid >> 5, lid = tid & 31;

    double local_acc = 0.0;                          // meaningful on tid 0

    for (int row = blockIdx.x; row < B; row += gridDim.x) {
        const float4* rowp = dist + (size_t)row * NUM_C;
        const int lbl = labels_are_i32 ? labels_raw[row]
                                       : labels_raw[2 * row];

        // front-batched loads: 4 independent LDG.128 per thread
        const int c0 = tid, c1 = tid + THREADS,
                  c2 = tid + 2 * THREADS, c3 = tid + 3 * THREADS;
        float4 v0 = __ldcs(rowp + c0);
        float4 v1 = __ldcs(rowp + c1);
        float4 v2 = __ldcs(rowp + c2);
        float4 v3 = make_float4(0.f, 0.f, 0.f, 0.f);
        const bool has3 = (c3 < NUM_C);
        if (has3) v3 = __ldcs(rowp + c3);

        float d0 = softmin4(v0);
        float d1 = softmin4(v1);
        float d2 = softmin4(v2);
        float d3 = has3 ? softmin4(v3) : 0.0f;

        float sum_d = (d0 + d1) + (d2 + d3);
        float in_cls = 0.0f;
        if (c0 == lbl) in_cls = d0;
        if (c1 == lbl) in_cls = d1;
        if (c2 == lbl) in_cls = d2;
        if (c3 == lbl) in_cls = d3;

        // warp reduce (in_cls nonzero on exactly one thread)
#pragma unroll
        for (int off = 16; off > 0; off >>= 1) {
            sum_d  += __shfl_xor_sync(0xFFFFFFFFu, sum_d,  off);
            in_cls += __shfl_xor_sync(0xFFFFFFFFu, in_cls, off);
        }
        if (lid == 0) { s_sum[wid] = sum_d; s_in[wid] = in_cls; }
        __syncthreads();

        if (tid == 0) {
            float tot = 0.0f, inc = 0.0f;
#pragma unroll
            for (int w = 0; w < THREADS / 32; w++) { tot += s_sum[w]; inc += s_in[w]; }
            float out_mean = (tot - inc) * (1.0f / (NUM_C - 1));
            float r = inc / out_mean;
            local_acc += (double)(r * r);
        }
        __syncthreads();   // protect shared reuse next row
    }

    if (tid == 0) {
        atomicAdd(&g_acc, local_acc);
        __threadfence();
        unsigned t = atomicAdd(&g_count, 1u);
        if (t == gridDim.x - 1) {            // last block: finalize + reset
            double a = atomicAdd(&g_acc, 0.0);   // L2-coherent read
            *out = (float)(a / (double)B);
            g_acc   = 0.0;                   // restore invariant for replay
            g_count = 0u;
        }
    }
}

extern "C" void kernel_launch(void* const* d_in, const int* in_sizes, int n_in,
                              void* d_out, int out_size) {
    const float4* dist   = (const float4*)d_in[0];
    const int*    labels = (const int*)d_in[1];
    float*        out    = (float*)d_out;
    const int B = in_sizes[1];   // label element count == batch size

    mpl_kernel<<<GRID, THREADS>>>(dist, labels, out, B);
}